// round 8
// baseline (speedup 1.0000x reference)
#include <cuda_runtime.h>
#include <cuda_bf16.h>

// Problem shape (fixed per problem instance)
#define B_MAX 16
#define S_DIM 4096
#define D_DIM 512
#define D4 (D_DIM / 4)                       // 128 float4 per row
#define NCHUNK 32                            // row chunks per batch
#define ROWS_PER_CHUNK (S_DIM / NCHUNK)      // 128
#define THREADS 128                          // one float4 column-slot per thread

// Deterministic partial-sum scratch: [B][NCHUNK][D] floats = 1 MiB (L2-resident)
__device__ float4 g_scratch[B_MAX * NCHUNK * D4];

// xs_len may be int32 (JAX x64-disabled downcast) or int64.
// Little-endian sniff: word[1] is the high half of len[0] if int64 (== 0,
// since len <= 4096), or len[1] if int32 (in [1,4096], != 0).
__device__ __forceinline__ long long read_len(const void* p, int b)
{
    const int* p32 = (const int*)p;
    if (p32[1] == 0) {
        return ((const long long*)p)[b];   // int64 layout
    } else {
        return (long long)p32[b];          // int32 layout
    }
}

__global__ __launch_bounds__(THREADS)
void mean_accum_kernel(const float* __restrict__ xs,
                       const void* __restrict__ xs_len)
{
    const int chunk = blockIdx.x;        // 0..NCHUNK-1
    const int b     = blockIdx.y;        // 0..B-1
    const int t     = threadIdx.x;       // 0..127 -> float4 column slot

    const long long L = read_len(xs_len, b);
    const int r0 = chunk * ROWS_PER_CHUNK;
    int r1 = r0 + ROWS_PER_CHUNK;
    if ((long long)r1 > L) r1 = (int)L;

    float4* outp = &g_scratch[(b * NCHUNK + chunk) * D4 + t];

    if (r0 >= r1) {
        *outp = make_float4(0.f, 0.f, 0.f, 0.f);
        return;
    }

    const float4* base = reinterpret_cast<const float4*>(
        xs + (size_t)b * S_DIM * D_DIM) + t;

    float4 a0 = make_float4(0.f, 0.f, 0.f, 0.f);
    float4 a1 = make_float4(0.f, 0.f, 0.f, 0.f);
    float4 a2 = make_float4(0.f, 0.f, 0.f, 0.f);
    float4 a3 = make_float4(0.f, 0.f, 0.f, 0.f);

    int r = r0;
    // 8 independent LDG.128 front-batched per iteration -> MLP ~8/thread
    for (; r + 8 <= r1; r += 8) {
        float4 v0 = base[(size_t)(r + 0) * D4];
        float4 v1 = base[(size_t)(r + 1) * D4];
        float4 v2 = base[(size_t)(r + 2) * D4];
        float4 v3 = base[(size_t)(r + 3) * D4];
        float4 v4 = base[(size_t)(r + 4) * D4];
        float4 v5 = base[(size_t)(r + 5) * D4];
        float4 v6 = base[(size_t)(r + 6) * D4];
        float4 v7 = base[(size_t)(r + 7) * D4];
        a0.x += v0.x; a0.y += v0.y; a0.z += v0.z; a0.w += v0.w;
        a1.x += v1.x; a1.y += v1.y; a1.z += v1.z; a1.w += v1.w;
        a2.x += v2.x; a2.y += v2.y; a2.z += v2.z; a2.w += v2.w;
        a3.x += v3.x; a3.y += v3.y; a3.z += v3.z; a3.w += v3.w;
        a0.x += v4.x; a0.y += v4.y; a0.z += v4.z; a0.w += v4.w;
        a1.x += v5.x; a1.y += v5.y; a1.z += v5.z; a1.w += v5.w;
        a2.x += v6.x; a2.y += v6.y; a2.z += v6.z; a2.w += v6.w;
        a3.x += v7.x; a3.y += v7.y; a3.z += v7.z; a3.w += v7.w;
    }
    for (; r < r1; r++) {
        float4 v = base[(size_t)r * D4];
        a0.x += v.x; a0.y += v.y; a0.z += v.z; a0.w += v.w;
    }

    float4 acc;
    acc.x = (a0.x + a1.x) + (a2.x + a3.x);
    acc.y = (a0.y + a1.y) + (a2.y + a3.y);
    acc.z = (a0.z + a1.z) + (a2.z + a3.z);
    acc.w = (a0.w + a1.w) + (a2.w + a3.w);

    *outp = acc;
}

// Finish: grid (32, B) = 512 CTAs, 128 threads.
// Warp w of CTA x owns float4 column (x*4 + w); lane l owns chunk l.
// One LDG.128 per thread from L2-hot scratch, then a fixed-order shfl
// butterfly (deterministic), lane 0 scales and stores.
__global__ __launch_bounds__(THREADS)
void mean_finish_kernel(const void* __restrict__ xs_len,
                        float* __restrict__ out)
{
    const int b    = blockIdx.y;
    const int col  = blockIdx.x * 4 + (threadIdx.x >> 5);  // 0..127
    const int lane = threadIdx.x & 31;                     // chunk index

    float4 v = g_scratch[(b * NCHUNK + lane) * D4 + col];

    #pragma unroll
    for (int off = 16; off > 0; off >>= 1) {
        v.x += __shfl_xor_sync(0xFFFFFFFFu, v.x, off);
        v.y += __shfl_xor_sync(0xFFFFFFFFu, v.y, off);
        v.z += __shfl_xor_sync(0xFFFFFFFFu, v.z, off);
        v.w += __shfl_xor_sync(0xFFFFFFFFu, v.w, off);
    }

    if (lane == 0) {
        const float inv = 1.0f / (float)read_len(xs_len, b);
        v.x *= inv; v.y *= inv; v.z *= inv; v.w *= inv;
        reinterpret_cast<float4*>(out + (size_t)b * D_DIM)[col] = v;
    }
}

extern "C" void kernel_launch(void* const* d_in, const int* in_sizes, int n_in,
                              void* d_out, int out_size)
{
    const float* xs     = (const float*)d_in[0];
    const void*  xs_len = d_in[1];
    float*       out    = (float*)d_out;

    const int B = in_sizes[1];   // number of sequences (16)

    dim3 grid1(NCHUNK, B);
    mean_accum_kernel<<<grid1, THREADS>>>(xs, xs_len);

    dim3 grid2(32, B);
    mean_finish_kernel<<<grid2, THREADS>>>(xs_len, out);
}

// round 9
// speedup vs baseline: 1.3064x; 1.3064x over previous
#include <cuda_runtime.h>
#include <cuda_bf16.h>

// Problem shape (fixed per problem instance)
#define B_MAX 16
#define S_DIM 4096
#define D_DIM 512
#define D4 (D_DIM / 4)                       // 128 float4 per row
#define NCHUNK 64                            // strided row-groups per batch
#define THREADS 128                          // one float4 column-slot per thread

// Deterministic partial-sum scratch: [B][NCHUNK][D] floats = 2 MiB (L2-resident)
__device__ float4 g_scratch[B_MAX * NCHUNK * D4];

// xs_len may be int32 (JAX x64-disabled downcast) or int64.
// Little-endian sniff: word[1] is the high half of len[0] if int64 (== 0,
// since len <= 4096), or len[1] if int32 (in [1,4096], != 0).
__device__ __forceinline__ long long read_len(const void* p, int b)
{
    const int* p32 = (const int*)p;
    if (p32[1] == 0) {
        return ((const long long*)p)[b];   // int64 layout
    } else {
        return (long long)p32[b];          // int32 layout
    }
}

// Accum: grid (B, NCHUNK). Chunk c of batch b sums rows {c, c+64, c+128, ...} < L.
// -> every chunk of a batch does ceil(L/64) +- 1 rows: balanced.
// Batch is the fast grid axis so adjacent SMs hold different batches.
__global__ __launch_bounds__(THREADS)
void mean_accum_kernel(const float* __restrict__ xs,
                       const void* __restrict__ xs_len)
{
    const int b     = blockIdx.x;        // 0..B-1 (fast axis)
    const int chunk = blockIdx.y;        // 0..NCHUNK-1
    const int t     = threadIdx.x;       // 0..127 -> float4 column slot

    const long long L = read_len(xs_len, b);
    // number of rows this chunk owns: rows r = chunk + k*NCHUNK < L
    const int n = (int)((L - chunk + NCHUNK - 1) / NCHUNK > 0
                        ? (L - chunk + NCHUNK - 1) / NCHUNK : 0);

    float4* outp = &g_scratch[(b * NCHUNK + chunk) * D4 + t];

    if (n <= 0) {
        *outp = make_float4(0.f, 0.f, 0.f, 0.f);
        return;
    }

    // base pointer at row 'chunk'; successive owned rows step NCHUNK rows
    const float4* p = reinterpret_cast<const float4*>(
        xs + (size_t)b * S_DIM * D_DIM + (size_t)chunk * D_DIM) + t;
    const size_t step = (size_t)NCHUNK * D4;   // float4 elements per stride

    float4 a0 = make_float4(0.f, 0.f, 0.f, 0.f);
    float4 a1 = make_float4(0.f, 0.f, 0.f, 0.f);
    float4 a2 = make_float4(0.f, 0.f, 0.f, 0.f);
    float4 a3 = make_float4(0.f, 0.f, 0.f, 0.f);

    int k = 0;
    // 8 independent LDG.128 front-batched per iteration -> MLP ~8/thread
    for (; k + 8 <= n; k += 8) {
        const float4* q = p + (size_t)k * step;
        float4 v0 = q[0 * step];
        float4 v1 = q[1 * step];
        float4 v2 = q[2 * step];
        float4 v3 = q[3 * step];
        float4 v4 = q[4 * step];
        float4 v5 = q[5 * step];
        float4 v6 = q[6 * step];
        float4 v7 = q[7 * step];
        a0.x += v0.x; a0.y += v0.y; a0.z += v0.z; a0.w += v0.w;
        a1.x += v1.x; a1.y += v1.y; a1.z += v1.z; a1.w += v1.w;
        a2.x += v2.x; a2.y += v2.y; a2.z += v2.z; a2.w += v2.w;
        a3.x += v3.x; a3.y += v3.y; a3.z += v3.z; a3.w += v3.w;
        a0.x += v4.x; a0.y += v4.y; a0.z += v4.z; a0.w += v4.w;
        a1.x += v5.x; a1.y += v5.y; a1.z += v5.z; a1.w += v5.w;
        a2.x += v6.x; a2.y += v6.y; a2.z += v6.z; a2.w += v6.w;
        a3.x += v7.x; a3.y += v7.y; a3.z += v7.z; a3.w += v7.w;
    }
    for (; k < n; k++) {
        float4 v = p[(size_t)k * step];
        a0.x += v.x; a0.y += v.y; a0.z += v.z; a0.w += v.w;
    }

    float4 acc;
    acc.x = (a0.x + a1.x) + (a2.x + a3.x);
    acc.y = (a0.y + a1.y) + (a2.y + a3.y);
    acc.z = (a0.z + a1.z) + (a2.z + a3.z);
    acc.w = (a0.w + a1.w) + (a2.w + a3.w);

    *outp = acc;
}

// Finish: grid (32, B) = 512 CTAs, 128 threads.
// Warp w of CTA x owns float4 column (x*4 + w); lane l owns chunks l and l+32.
// Two LDG.128 per thread from L2-hot scratch, fixed-order shfl butterfly
// (deterministic), lane 0 scales and stores.
__global__ __launch_bounds__(THREADS)
void mean_finish_kernel(const void* __restrict__ xs_len,
                        float* __restrict__ out)
{
    const int b    = blockIdx.y;
    const int col  = blockIdx.x * 4 + (threadIdx.x >> 5);  // 0..127
    const int lane = threadIdx.x & 31;

    float4 u = g_scratch[(b * NCHUNK + lane) * D4 + col];
    float4 w = g_scratch[(b * NCHUNK + lane + 32) * D4 + col];
    float4 v;
    v.x = u.x + w.x; v.y = u.y + w.y; v.z = u.z + w.z; v.w = u.w + w.w;

    #pragma unroll
    for (int off = 16; off > 0; off >>= 1) {
        v.x += __shfl_xor_sync(0xFFFFFFFFu, v.x, off);
        v.y += __shfl_xor_sync(0xFFFFFFFFu, v.y, off);
        v.z += __shfl_xor_sync(0xFFFFFFFFu, v.z, off);
        v.w += __shfl_xor_sync(0xFFFFFFFFu, v.w, off);
    }

    if (lane == 0) {
        const float inv = 1.0f / (float)read_len(xs_len, b);
        v.x *= inv; v.y *= inv; v.z *= inv; v.w *= inv;
        reinterpret_cast<float4*>(out + (size_t)b * D_DIM)[col] = v;
    }
}

extern "C" void kernel_launch(void* const* d_in, const int* in_sizes, int n_in,
                              void* d_out, int out_size)
{
    const float* xs     = (const float*)d_in[0];
    const void*  xs_len = d_in[1];
    float*       out    = (float*)d_out;

    const int B = in_sizes[1];   // number of sequences (16)

    dim3 grid1(B, NCHUNK);
    mean_accum_kernel<<<grid1, THREADS>>>(xs, xs_len);

    dim3 grid2(32, B);
    mean_finish_kernel<<<grid2, THREADS>>>(xs_len, out);
}

// round 10
// speedup vs baseline: 1.3325x; 1.0200x over previous
#include <cuda_runtime.h>
#include <cuda_bf16.h>

// Problem shape (fixed per problem instance)
#define B_MAX 16
#define S_DIM 4096
#define D_DIM 512
#define D4 (D_DIM / 4)                       // 128 float4 per row
#define NCHUNK 128                           // strided row-groups per batch
#define THREADS 128                          // one float4 column-slot per thread

// Deterministic partial-sum scratch: [B][NCHUNK][D] floats = 4 MiB (L2-resident)
__device__ float4 g_scratch[B_MAX * NCHUNK * D4];

// xs_len may be int32 (JAX x64-disabled downcast) or int64.
// Little-endian sniff: word[1] is the high half of len[0] if int64 (== 0,
// since len <= 4096), or len[1] if int32 (in [1,4096], != 0).
__device__ __forceinline__ long long read_len(const void* p, int b)
{
    const int* p32 = (const int*)p;
    if (p32[1] == 0) {
        return ((const long long*)p)[b];   // int64 layout
    } else {
        return (long long)p32[b];          // int32 layout
    }
}

// Accum: grid (B, NCHUNK). Chunk c of batch b sums rows {c, c+128, c+256, ...} < L.
// -> every chunk of a batch does ceil(L/128) +- 1 rows (max 32): fine-grained,
// balanced within a batch. Batch is the fast grid axis so adjacent bids are
// different batches -> resident CTAs on an SM mix long and short batches.
__global__ __launch_bounds__(THREADS)
void mean_accum_kernel(const float* __restrict__ xs,
                       const void* __restrict__ xs_len)
{
    const int b     = blockIdx.x;        // 0..B-1 (fast axis)
    const int chunk = blockIdx.y;        // 0..NCHUNK-1
    const int t     = threadIdx.x;       // 0..127 -> float4 column slot

    const long long L = read_len(xs_len, b);
    // rows r = chunk + k*NCHUNK < L  ->  n = ceil((L - chunk)/NCHUNK), clamped
    long long nll = (L - chunk + NCHUNK - 1) / NCHUNK;
    const int n = nll > 0 ? (int)nll : 0;

    float4* outp = &g_scratch[(b * NCHUNK + chunk) * D4 + t];

    if (n <= 0) {
        *outp = make_float4(0.f, 0.f, 0.f, 0.f);
        return;
    }

    const float4* p = reinterpret_cast<const float4*>(
        xs + (size_t)b * S_DIM * D_DIM + (size_t)chunk * D_DIM) + t;
    const size_t step = (size_t)NCHUNK * D4;   // float4 elements per row-stride

    float4 a0 = make_float4(0.f, 0.f, 0.f, 0.f);
    float4 a1 = make_float4(0.f, 0.f, 0.f, 0.f);
    float4 a2 = make_float4(0.f, 0.f, 0.f, 0.f);
    float4 a3 = make_float4(0.f, 0.f, 0.f, 0.f);

    int k = 0;
    // 8 independent LDG.128 front-batched per iteration -> MLP ~8/thread
    for (; k + 8 <= n; k += 8) {
        const float4* q = p + (size_t)k * step;
        float4 v0 = q[0 * step];
        float4 v1 = q[1 * step];
        float4 v2 = q[2 * step];
        float4 v3 = q[3 * step];
        float4 v4 = q[4 * step];
        float4 v5 = q[5 * step];
        float4 v6 = q[6 * step];
        float4 v7 = q[7 * step];
        a0.x += v0.x; a0.y += v0.y; a0.z += v0.z; a0.w += v0.w;
        a1.x += v1.x; a1.y += v1.y; a1.z += v1.z; a1.w += v1.w;
        a2.x += v2.x; a2.y += v2.y; a2.z += v2.z; a2.w += v2.w;
        a3.x += v3.x; a3.y += v3.y; a3.z += v3.z; a3.w += v3.w;
        a0.x += v4.x; a0.y += v4.y; a0.z += v4.z; a0.w += v4.w;
        a1.x += v5.x; a1.y += v5.y; a1.z += v5.z; a1.w += v5.w;
        a2.x += v6.x; a2.y += v6.y; a2.z += v6.z; a2.w += v6.w;
        a3.x += v7.x; a3.y += v7.y; a3.z += v7.z; a3.w += v7.w;
    }
    for (; k < n; k++) {
        float4 v = p[(size_t)k * step];
        a0.x += v.x; a0.y += v.y; a0.z += v.z; a0.w += v.w;
    }

    float4 acc;
    acc.x = (a0.x + a1.x) + (a2.x + a3.x);
    acc.y = (a0.y + a1.y) + (a2.y + a3.y);
    acc.z = (a0.z + a1.z) + (a2.z + a3.z);
    acc.w = (a0.w + a1.w) + (a2.w + a3.w);

    *outp = acc;
}

// Finish: grid (32, B) = 512 CTAs, 128 threads.
// Warp w of CTA x owns float4 column (x*4 + w); lane l owns chunks
// {l, l+32, l+64, l+96}. Four LDG.128 per thread from L2-hot scratch,
// fixed-order pairwise combine + shfl butterfly (deterministic).
__global__ __launch_bounds__(THREADS)
void mean_finish_kernel(const void* __restrict__ xs_len,
                        float* __restrict__ out)
{
    const int b    = blockIdx.y;
    const int col  = blockIdx.x * 4 + (threadIdx.x >> 5);  // 0..127
    const int lane = threadIdx.x & 31;

    const float4* src = &g_scratch[(size_t)b * NCHUNK * D4 + col];
    float4 u0 = src[(lane +  0) * D4];
    float4 u1 = src[(lane + 32) * D4];
    float4 u2 = src[(lane + 64) * D4];
    float4 u3 = src[(lane + 96) * D4];

    float4 v;
    v.x = (u0.x + u1.x) + (u2.x + u3.x);
    v.y = (u0.y + u1.y) + (u2.y + u3.y);
    v.z = (u0.z + u1.z) + (u2.z + u3.z);
    v.w = (u0.w + u1.w) + (u2.w + u3.w);

    #pragma unroll
    for (int off = 16; off > 0; off >>= 1) {
        v.x += __shfl_xor_sync(0xFFFFFFFFu, v.x, off);
        v.y += __shfl_xor_sync(0xFFFFFFFFu, v.y, off);
        v.z += __shfl_xor_sync(0xFFFFFFFFu, v.z, off);
        v.w += __shfl_xor_sync(0xFFFFFFFFu, v.w, off);
    }

    if (lane == 0) {
        const float inv = 1.0f / (float)read_len(xs_len, b);
        v.x *= inv; v.y *= inv; v.z *= inv; v.w *= inv;
        reinterpret_cast<float4*>(out + (size_t)b * D_DIM)[col] = v;
    }
}

extern "C" void kernel_launch(void* const* d_in, const int* in_sizes, int n_in,
                              void* d_out, int out_size)
{
    const float* xs     = (const float*)d_in[0];
    const void*  xs_len = d_in[1];
    float*       out    = (float*)d_out;

    const int B = in_sizes[1];   // number of sequences (16)

    dim3 grid1(B, NCHUNK);
    mean_accum_kernel<<<grid1, THREADS>>>(xs, xs_len);

    dim3 grid2(32, B);
    mean_finish_kernel<<<grid2, THREADS>>>(xs_len, out);
}